// round 14
// baseline (speedup 1.0000x reference)
#include <cuda_runtime.h>
#include <cuda_bf16.h>

#define BB 64
#define DD 512
#define HH 8
#define EPSF 1e-8f
#define LOG2E 1.4426950408889634f
#define INV_SQRT_D 0.04419417382415922f  // 1/sqrt(512)

// Deterministic scratch for per-head attended values: att[h][b][d]  (1 MB).
// 16B-aligned so the float4 loads in the reduce kernel are unconditionally legal.
__device__ __align__(16) float g_att[HH * BB * DD];

__device__ __forceinline__ float frcp(float x) {
    float y; asm("rcp.approx.f32 %0, %1;" : "=f"(y) : "f"(x)); return y;
}
__device__ __forceinline__ float fex2(float x) {
    float y; asm("ex2.approx.f32 %0, %1;" : "=f"(y) : "f"(x)); return y;
}

// grid = (B, H, 2); 256 threads; thread t handles row i = z*256 + t of the
// 512x512 score matrix for its (h, b).
__global__ __launch_bounds__(256)
void FLAttention_attn_kernel(const float* __restrict__ x,
                             const float* __restrict__ alphas,
                             const float* __restrict__ betas) {
    __shared__ float qs[DD];
    __shared__ float vs[DD];

    const int b   = blockIdx.x;
    const int h   = blockIdx.y;
    const int hal = blockIdx.z;
    const int tid = threadIdx.x;

    const float aq = alphas[h * 3 + 0];
    const float ak = alphas[h * 3 + 1];
    const float av = alphas[h * 3 + 2];
    const float bq = betas[h * 3 + 0];
    const float bk = betas[h * 3 + 1];
    const float bv = betas[h * 3 + 2];

    const float* xrow = x + b * DD;

    // Build q and v rows in shared memory (each thread fills 2 slots).
#pragma unroll
    for (int t = 0; t < 2; t++) {
        int j = tid + t * 256;
        float xv = xrow[j];
        qs[j] = fmaf(aq, xv, bq);
        vs[j] = fmaf(av, xv, bv);
    }
    __syncthreads();

    const int   i  = hal * 256 + tid;
    const float ki = fmaf(ak, xrow[i], bk);

    const float4* q4 = reinterpret_cast<const float4*>(qs);
    const float4* v4 = reinterpret_cast<const float4*>(vs);

    // ---- Pass 1: dmin = min_j |q_j - k_i|  (fixed-pipe only, no MUFU) ----
    float m0 = 3.4e38f, m1 = 3.4e38f, m2 = 3.4e38f, m3 = 3.4e38f;
#pragma unroll 4
    for (int j4 = 0; j4 < DD / 4; j4++) {
        float4 q = q4[j4];
        m0 = fminf(m0, fabsf(q.x - ki));
        m1 = fminf(m1, fabsf(q.y - ki));
        m2 = fminf(m2, fabsf(q.z - ki));
        m3 = fminf(m3, fabsf(q.w - ki));
    }
    float dmin = fminf(fminf(m0, m1), fminf(m2, m3));
    // row max of 1/diff, pre-scaled by log2(e) so pass 2 is a single FFMA.
    // Computed with the SAME instruction sequence as the per-element logits,
    // so the argmin element's exponent is exactly 0 -> no overflow possible.
    const float mL = frcp(dmin + EPSF) * LOG2E;

    // ---- Pass 2: stable softmax-weighted sum of v ----
    float se0 = 0.f, se1 = 0.f, se2 = 0.f, se3 = 0.f;
    float sv0 = 0.f, sv1 = 0.f, sv2 = 0.f, sv3 = 0.f;
#pragma unroll 4
    for (int j4 = 0; j4 < DD / 4; j4++) {
        float4 q = q4[j4];
        float4 v = v4[j4];
        float e0 = fex2(fmaf(frcp(fabsf(q.x - ki) + EPSF), LOG2E, -mL));
        float e1 = fex2(fmaf(frcp(fabsf(q.y - ki) + EPSF), LOG2E, -mL));
        float e2 = fex2(fmaf(frcp(fabsf(q.z - ki) + EPSF), LOG2E, -mL));
        float e3 = fex2(fmaf(frcp(fabsf(q.w - ki) + EPSF), LOG2E, -mL));
        se0 += e0; sv0 = fmaf(e0, v.x, sv0);
        se1 += e1; sv1 = fmaf(e1, v.y, sv1);
        se2 += e2; sv2 = fmaf(e2, v.z, sv2);
        se3 += e3; sv3 = fmaf(e3, v.w, sv3);
    }
    float se  = (se0 + se1) + (se2 + se3);
    float sev = (sv0 + sv1) + (sv2 + sv3);

    g_att[(h * BB + b) * DD + i] = sev * frcp(se) * INV_SQRT_D;
}

// out[b,d] = x[b,d] + sum_h att[h,b,d] — deterministic reduction, float4-wide.
__global__ __launch_bounds__(256)
void FLAttention_reduce_kernel(const float* __restrict__ x,
                               float* __restrict__ out) {
    int idx = blockIdx.x * blockDim.x + threadIdx.x;  // over (B*D)/4 = 8192
    const float4* x4 = reinterpret_cast<const float4*>(x);
    float4 s = x4[idx];
#pragma unroll
    for (int h = 0; h < HH; h++) {
        const float4* a4 = reinterpret_cast<const float4*>(g_att + h * (BB * DD));
        float4 a = a4[idx];
        s.x += a.x; s.y += a.y; s.z += a.z; s.w += a.w;
    }
    reinterpret_cast<float4*>(out)[idx] = s;
}

extern "C" void kernel_launch(void* const* d_in, const int* in_sizes, int n_in,
                              void* d_out, int out_size) {
    const float* x      = (const float*)d_in[0];
    const float* alphas = (const float*)d_in[1];
    const float* betas  = (const float*)d_in[2];
    float*       out    = (float*)d_out;

    dim3 grid(BB, HH, 2);
    FLAttention_attn_kernel<<<grid, 256>>>(x, alphas, betas);
    FLAttention_reduce_kernel<<<(BB * DD) / (256 * 4), 256>>>(x, out);
}

// round 15
// speedup vs baseline: 1.0034x; 1.0034x over previous
#include <cuda_runtime.h>
#include <cuda_bf16.h>

#define BB 64
#define DD 512
#define HH 8
#define EPSF 1e-8f
#define LOG2E 1.4426950408889634f
#define INV_SQRT_D 0.04419417382415922f  // 1/sqrt(512)

// Deterministic scratch for per-head attended values: att[h][b][d]  (1 MB).
// 16B-aligned so the float4 loads in the reduce kernel are unconditionally legal.
__device__ __align__(16) float g_att[HH * BB * DD];

__device__ __forceinline__ float frcp(float x) {
    float y; asm("rcp.approx.f32 %0, %1;" : "=f"(y) : "f"(x)); return y;
}
__device__ __forceinline__ float fex2(float x) {
    float y; asm("ex2.approx.f32 %0, %1;" : "=f"(y) : "f"(x)); return y;
}

// grid = (B, H, 2); 256 threads; thread t handles row i = z*256 + t of the
// 512x512 score matrix for its (h, b).
__global__ __launch_bounds__(256)
void FLAttention_attn_kernel(const float* __restrict__ x,
                             const float* __restrict__ alphas,
                             const float* __restrict__ betas) {
    __shared__ float qs[DD];
    __shared__ float vs[DD];

    const int b   = blockIdx.x;
    const int h   = blockIdx.y;
    const int hal = blockIdx.z;
    const int tid = threadIdx.x;

    const float aq = alphas[h * 3 + 0];
    const float ak = alphas[h * 3 + 1];
    const float av = alphas[h * 3 + 2];
    const float bq = betas[h * 3 + 0];
    const float bk = betas[h * 3 + 1];
    const float bv = betas[h * 3 + 2];

    const float* xrow = x + b * DD;

    // Build q and v rows in shared memory (each thread fills 2 slots).
#pragma unroll
    for (int t = 0; t < 2; t++) {
        int j = tid + t * 256;
        float xv = xrow[j];
        qs[j] = fmaf(aq, xv, bq);
        vs[j] = fmaf(av, xv, bv);
    }
    __syncthreads();

    const int   i  = hal * 256 + tid;
    const float ki = fmaf(ak, xrow[i], bk);

    const float4* q4 = reinterpret_cast<const float4*>(qs);
    const float4* v4 = reinterpret_cast<const float4*>(vs);

    // ---- Pass 1: dmin = min_j |q_j - k_i|  (fixed-pipe only, no MUFU) ----
    float m0 = 3.4e38f, m1 = 3.4e38f, m2 = 3.4e38f, m3 = 3.4e38f;
#pragma unroll 4
    for (int j4 = 0; j4 < DD / 4; j4++) {
        float4 q = q4[j4];
        m0 = fminf(m0, fabsf(q.x - ki));
        m1 = fminf(m1, fabsf(q.y - ki));
        m2 = fminf(m2, fabsf(q.z - ki));
        m3 = fminf(m3, fabsf(q.w - ki));
    }
    float dmin = fminf(fminf(m0, m1), fminf(m2, m3));
    // row max of 1/diff, pre-scaled by log2(e) so pass 2 is a single FFMA.
    // Computed with the SAME instruction sequence as the per-element logits,
    // so the argmin element's exponent is exactly 0 -> no overflow possible.
    const float mL = frcp(dmin + EPSF) * LOG2E;

    // ---- Pass 2: stable softmax-weighted sum of v ----
    float se0 = 0.f, se1 = 0.f, se2 = 0.f, se3 = 0.f;
    float sv0 = 0.f, sv1 = 0.f, sv2 = 0.f, sv3 = 0.f;
#pragma unroll 4
    for (int j4 = 0; j4 < DD / 4; j4++) {
        float4 q = q4[j4];
        float4 v = v4[j4];
        float e0 = fex2(fmaf(frcp(fabsf(q.x - ki) + EPSF), LOG2E, -mL));
        float e1 = fex2(fmaf(frcp(fabsf(q.y - ki) + EPSF), LOG2E, -mL));
        float e2 = fex2(fmaf(frcp(fabsf(q.z - ki) + EPSF), LOG2E, -mL));
        float e3 = fex2(fmaf(frcp(fabsf(q.w - ki) + EPSF), LOG2E, -mL));
        se0 += e0; sv0 = fmaf(e0, v.x, sv0);
        se1 += e1; sv1 = fmaf(e1, v.y, sv1);
        se2 += e2; sv2 = fmaf(e2, v.z, sv2);
        se3 += e3; sv3 = fmaf(e3, v.w, sv3);
    }
    float se  = (se0 + se1) + (se2 + se3);
    float sev = (sv0 + sv1) + (sv2 + sv3);

    g_att[(h * BB + b) * DD + i] = sev * frcp(se) * INV_SQRT_D;
}

// out[b,d] = x[b,d] + sum_h att[h,b,d] — deterministic reduction, float4-wide.
// 64-thread blocks spread the 73728 LDG.128s over 128 SMs instead of 32:
// LSU-issue floor per SM drops 4x (measured 5.18us at grid=32, occ=12%).
__global__ __launch_bounds__(64)
void FLAttention_reduce_kernel(const float* __restrict__ x,
                               float* __restrict__ out) {
    int idx = blockIdx.x * blockDim.x + threadIdx.x;  // over (B*D)/4 = 8192
    const float4* x4 = reinterpret_cast<const float4*>(x);
    float4 s = x4[idx];
#pragma unroll
    for (int h = 0; h < HH; h++) {
        const float4* a4 = reinterpret_cast<const float4*>(g_att + h * (BB * DD));
        float4 a = a4[idx];
        s.x += a.x; s.y += a.y; s.z += a.z; s.w += a.w;
    }
    reinterpret_cast<float4*>(out)[idx] = s;
}

extern "C" void kernel_launch(void* const* d_in, const int* in_sizes, int n_in,
                              void* d_out, int out_size) {
    const float* x      = (const float*)d_in[0];
    const float* alphas = (const float*)d_in[1];
    const float* betas  = (const float*)d_in[2];
    float*       out    = (float*)d_out;

    dim3 grid(BB, HH, 2);
    FLAttention_attn_kernel<<<grid, 256>>>(x, alphas, betas);
    FLAttention_reduce_kernel<<<(BB * DD) / (64 * 4), 64>>>(x, out);
}